// round 8
// baseline (speedup 1.0000x reference)
#include <cuda_runtime.h>
#include <cuda_fp16.h>
#include <cstdint>
#include <cstddef>

// ---------------- scratch ----------------
__device__ float g_Q[4096u * 4096u];
__device__ float g_K[4096u * 1024u];
__device__ float g_V[4096u * 1024u];
__device__ float g_ctx[4096u * 4096u];

// ---------------- helpers ----------------
__device__ __forceinline__ uint32_t f2tf(float x) {
    uint32_t u;
    asm("cvt.rna.tf32.f32 %0, %1;" : "=r"(u) : "f"(x));
    return u;
}
__device__ __forceinline__ float4 tf4(float4 v) {
    float4 t;
    t.x = __uint_as_float(f2tf(v.x)); t.y = __uint_as_float(f2tf(v.y));
    t.z = __uint_as_float(f2tf(v.z)); t.w = __uint_as_float(f2tf(v.w));
    return t;
}
__device__ __forceinline__ uint32_t smem_u32(const void* p) {
    uint32_t a;
    asm("{ .reg .u64 t; cvta.to.shared.u64 t, %1; cvt.u32.u64 %0, t; }" : "=r"(a) : "l"(p));
    return a;
}
__device__ __forceinline__ void mma_tf32(float* c, uint32_t a0, uint32_t a1,
                                         uint32_t a2, uint32_t a3,
                                         uint32_t b0, uint32_t b1) {
    asm volatile(
        "mma.sync.aligned.m16n8k8.row.col.f32.tf32.tf32.f32 "
        "{%0,%1,%2,%3}, {%4,%5,%6,%7}, {%8,%9}, {%0,%1,%2,%3};\n"
        : "+f"(c[0]), "+f"(c[1]), "+f"(c[2]), "+f"(c[3])
        : "r"(a0), "r"(a1), "r"(a2), "r"(a3), "r"(b0), "r"(b1));
}
__device__ __forceinline__ void mma_f16(float* c, uint32_t a0, uint32_t a1,
                                        uint32_t a2, uint32_t a3,
                                        uint32_t b0, uint32_t b1) {
    asm volatile(
        "mma.sync.aligned.m16n8k16.row.col.f32.f16.f16.f32 "
        "{%0,%1,%2,%3}, {%4,%5,%6,%7}, {%8,%9}, {%0,%1,%2,%3};\n"
        : "+f"(c[0]), "+f"(c[1]), "+f"(c[2]), "+f"(c[3])
        : "r"(a0), "r"(a1), "r"(a2), "r"(a3), "r"(b0), "r"(b1));
}
// load adjacent fp32 pair from smem, convert to packed half2
__device__ __forceinline__ uint32_t ldcvt(const float* p) {
    float2 v = *(const float2*)p;
    __half2 h = __floats2half2_rn(v.x, v.y);
    return *(uint32_t*)&h;
}
#define CP_ASYNC16(dst, src) \
    asm volatile("cp.async.cg.shared.global [%0], [%1], 16;" :: "r"(dst), "l"(src) : "memory")
#define CP_COMMIT() asm volatile("cp.async.commit_group;" ::: "memory")
#define CP_WAIT2()  asm volatile("cp.async.wait_group 2;" ::: "memory")

// =========================================================================
// FP16 GEMM (cp.async 4-stage):  C[M,N] = A[M,K] @ B[N,K]^T
// fp32 in smem (stride 40 floats: conflict-free LDS.64 fragment pairs),
// convert to half2 at fragment load. Block 128x128, K-tile 32, 256 thr,
// warp tile 64x32 = 4x4 mma(m16n8k16), fp32 accum.
// =========================================================================
#define GA_STR 40                        // 32 data + 8 pad floats (160B rows)
#define NST 4
#define STGF (2 * 128 * GA_STR)          // floats per stage (A then B)
#define GEMM_SMEM (NST * STGF * 4)       // 163840 bytes

__global__ void __launch_bounds__(256)
gemm_f16(float* __restrict__ C, const float* __restrict__ A,
         const float* __restrict__ B, int M, int N, int K)
{
    extern __shared__ float sm[];

    const int tid  = threadIdx.x;
    const int warp = tid >> 5, lane = tid & 31;
    const int wm = warp & 1, wn = warp >> 1;
    const int bm = blockIdx.y * 128, bn = blockIdx.x * 128;
    const int kTiles = K >> 5;

    const int r8 = tid >> 3;             // 0..31
    const int c8 = tid & 7;              // 0..7 (16B chunk)
    const uint32_t sbase = smem_u32(sm);

    auto issue = [&](int kt) {
        const int s = kt & (NST - 1);
        const uint32_t As = sbase + (uint32_t)(s * STGF) * 4;
        const uint32_t Bs = As + 128 * GA_STR * 4;
        const float* Ag = A + (size_t)bm * K + (size_t)kt * 32;
        const float* Bg = B + (size_t)bn * K + (size_t)kt * 32;
#pragma unroll
        for (int i = 0; i < 4; i++) {
            int r = r8 + i * 32;
            CP_ASYNC16(As + (uint32_t)(r * GA_STR + c8 * 4) * 4,
                       Ag + (size_t)r * K + c8 * 4);
        }
#pragma unroll
        for (int i = 0; i < 4; i++) {
            int r = r8 + i * 32;
            CP_ASYNC16(Bs + (uint32_t)(r * GA_STR + c8 * 4) * 4,
                       Bg + (size_t)r * K + c8 * 4);
        }
        CP_COMMIT();
    };

    float acc[4][4][4];
#pragma unroll
    for (int i = 0; i < 4; i++)
#pragma unroll
        for (int j = 0; j < 4; j++)
#pragma unroll
            for (int t = 0; t < 4; t++) acc[i][j][t] = 0.f;

    issue(0); issue(1); issue(2);

    for (int kt = 0; kt < kTiles; kt++) {
        CP_WAIT2();
        __syncthreads();
        if (kt + 3 < kTiles) issue(kt + 3);
        else CP_COMMIT();                 // keep group count in lockstep

        const float* As_ = sm + (kt & (NST - 1)) * STGF;
        const float* Bs_ = As_ + 128 * GA_STR;
#pragma unroll
        for (int ks = 0; ks < 2; ks++) {              // two k16 steps
            uint32_t a[4][4], b[4][2];
            const int c0 = ks * 16 + 2 * (lane & 3);
#pragma unroll
            for (int mt = 0; mt < 4; mt++) {
                int r0 = wm * 64 + mt * 16 + (lane >> 2);
                a[mt][0] = ldcvt(As_ + r0 * GA_STR + c0);
                a[mt][1] = ldcvt(As_ + (r0 + 8) * GA_STR + c0);
                a[mt][2] = ldcvt(As_ + r0 * GA_STR + c0 + 8);
                a[mt][3] = ldcvt(As_ + (r0 + 8) * GA_STR + c0 + 8);
            }
#pragma unroll
            for (int nt = 0; nt < 4; nt++) {
                int n0 = wn * 32 + nt * 8 + (lane >> 2);
                b[nt][0] = ldcvt(Bs_ + n0 * GA_STR + c0);
                b[nt][1] = ldcvt(Bs_ + n0 * GA_STR + c0 + 8);
            }
#pragma unroll
            for (int mt = 0; mt < 4; mt++)
#pragma unroll
                for (int nt = 0; nt < 4; nt++)
                    mma_f16(acc[mt][nt], a[mt][0], a[mt][1], a[mt][2], a[mt][3],
                            b[nt][0], b[nt][1]);
        }
        __syncthreads();
    }

#pragma unroll
    for (int mt = 0; mt < 4; mt++) {
        int r0 = bm + wm * 64 + mt * 16 + (lane >> 2);
#pragma unroll
        for (int nt = 0; nt < 4; nt++) {
            int c0 = bn + wn * 32 + nt * 8 + ((lane & 3) << 1);
            float* c = acc[mt][nt];
            *(float2*)(C + (size_t)r0 * N + c0)       = make_float2(c[0], c[1]);
            *(float2*)(C + (size_t)(r0 + 8) * N + c0) = make_float2(c[2], c[3]);
        }
    }
}

// =========================================================================
// Fused RoPE: Q heads (0..31) and K heads (32..39), grid (4096,10), blk (64,4)
// =========================================================================
__global__ void rope_all(float* __restrict__ Q, float* __restrict__ K)
{
    int tok = blockIdx.x;
    int hh  = blockIdx.y * 4 + threadIdx.y;
    int d   = threadIdx.x;
    int s   = tok & 2047;
    float inv = exp2f((float)d * -0.20762050593046f);
    float ang = (float)s * inv;
    float sn, cs;
    sincosf(ang, &sn, &cs);
    float* p = (hh < 32) ? (Q + (size_t)tok * 4096 + hh * 128)
                         : (K + (size_t)tok * 1024 + (hh - 32) * 128);
    float x1 = p[d], x2 = p[d + 64];
    p[d]      = x1 * cs - x2 * sn;
    p[d + 64] = x2 * cs + x1 * sn;
}

// =========================================================================
// Causal flash attention: f16 mma for QK^T (Q,K half2 in smem),
// fp32 softmax, tf32 mma for PV (V fp32-tf32 in smem). 256 threads.
// =========================================================================
#define QH_STR 68    // half2 per Q/K row (64 data + 4 pad)
#define VS_STR 136   // fp32 per V row
#define SS_STR 68    // fp32 per S row

__global__ void __launch_bounds__(256)
attn_kernel(float* __restrict__ ctx, const float* __restrict__ Qg,
            const float* __restrict__ Kg, const float* __restrict__ Vg)
{
    extern __shared__ float sm[];
    __half2* Qh = (__half2*)sm;                     // 64*68 half2 = 17408B
    __half2* Kh = Qh + 64 * QH_STR;                 // 17408B
    float* Vs   = (float*)(Kh + 64 * QH_STR);       // 64*136*4 = 34816B
    float* Ss   = Vs + 64 * VS_STR;                 // 64*68*4 = 17408B
    float* m_sm = Ss + 64 * SS_STR;
    float* l_sm = m_sm + 64;
    float* a_sm = l_sm + 64;

    const int tid  = threadIdx.x;
    const int warp = tid >> 5, lane = tid & 31;
    const int lq = lane >> 2;
    const int lr = lane & 3;
    const int qt = 31 - (int)blockIdx.x;
    const int h  = blockIdx.y;
    const int b  = blockIdx.z;
    const int hkv = h >> 2;
    const float scale = 0.08838834764831845f;

    const int mq = warp & 3;
    const int wh = warp >> 2;

    // ---- load Q tile (scaled, half2) ----
    const float* Qp = Qg + ((size_t)(b * 2048 + qt * 64)) * 4096 + h * 128;
#pragma unroll
    for (int i = 0; i < 8; i++) {
        int f = tid + i * 256;
        int r = f >> 5, c4 = (f & 31) << 2;
        float4 v = *(const float4*)(Qp + (size_t)r * 4096 + c4);
        __half2 h0 = __floats2half2_rn(v.x * scale, v.y * scale);
        __half2 h1 = __floats2half2_rn(v.z * scale, v.w * scale);
        __half2* p = Qh + r * QH_STR + (f & 31) * 2;
        p[0] = h0; p[1] = h1;
    }
    if (tid < 64) { m_sm[tid] = -3.0e38f; l_sm[tid] = 0.f; }

    float O[8][4];
#pragma unroll
    for (int i = 0; i < 8; i++)
#pragma unroll
        for (int j = 0; j < 4; j++) O[i][j] = 0.f;

    __syncthreads();

    for (int kt = 0; kt <= qt; kt++) {
        // ---- load K (half2) and V (tf32) tiles ----
        const float* Kp = Kg + ((size_t)(b * 2048 + kt * 64)) * 1024 + hkv * 128;
        const float* Vp = Vg + ((size_t)(b * 2048 + kt * 64)) * 1024 + hkv * 128;
#pragma unroll
        for (int i = 0; i < 8; i++) {
            int f = tid + i * 256;
            int r = f >> 5, c4 = (f & 31) << 2;
            float4 kv = *(const float4*)(Kp + (size_t)r * 1024 + c4);
            __half2 h0 = __floats2half2_rn(kv.x, kv.y);
            __half2 h1 = __floats2half2_rn(kv.z, kv.w);
            __half2* p = Kh + r * QH_STR + (f & 31) * 2;
            p[0] = h0; p[1] = h1;
            *(float4*)(Vs + r * VS_STR + c4) = tf4(*(const float4*)(Vp + (size_t)r * 1024 + c4));
        }
        __syncthreads();

        // ---- S = Q @ K^T via f16 mma ----
        {
            float sacc[4][4];
#pragma unroll
            for (int nt = 0; nt < 4; nt++)
#pragma unroll
                for (int t = 0; t < 4; t++) sacc[nt][t] = 0.f;

            const int r0 = mq * 16 + lq;
#pragma unroll
            for (int ks = 0; ks < 8; ks++) {         // 8 k16 steps over K=128
                int c0 = ks * 8 + lr;                 // half2 col
                uint32_t a0 = *(const uint32_t*)(Qh + r0 * QH_STR + c0);
                uint32_t a1 = *(const uint32_t*)(Qh + (r0 + 8) * QH_STR + c0);
                uint32_t a2 = *(const uint32_t*)(Qh + r0 * QH_STR + c0 + 4);
                uint32_t a3 = *(const uint32_t*)(Qh + (r0 + 8) * QH_STR + c0 + 4);
#pragma unroll
                for (int nt = 0; nt < 4; nt++) {
                    int n0 = wh * 32 + nt * 8 + lq;
                    uint32_t b0 = *(const uint32_t*)(Kh + n0 * QH_STR + c0);
                    uint32_t b1 = *(const uint32_t*)(Kh + n0 * QH_STR + c0 + 4);
                    mma_f16(sacc[nt], a0, a1, a2, a3, b0, b1);
                }
            }
            bool diag = (kt == qt);
#pragma unroll
            for (int nt = 0; nt < 4; nt++) {
                int c = wh * 32 + nt * 8 + 2 * lr;
                float v0 = sacc[nt][0], v1 = sacc[nt][1];
                float v2 = sacc[nt][2], v3 = sacc[nt][3];
                int ra = mq * 16 + lq, rb2 = ra + 8;
                if (diag) {
                    if (c > ra)      v0 = -3.0e38f;
                    if (c + 1 > ra)  v1 = -3.0e38f;
                    if (c > rb2)     v2 = -3.0e38f;
                    if (c + 1 > rb2) v3 = -3.0e38f;
                }
                *(float2*)(Ss + ra * SS_STR + c)  = make_float2(v0, v1);
                *(float2*)(Ss + rb2 * SS_STR + c) = make_float2(v2, v3);
            }
        }
        __syncthreads();

        // ---- online softmax (fp32), P stored tf32 ----
        {
            int row = tid >> 2, seg = tid & 3;
            float* srow = Ss + row * SS_STR;
            float mx = -3.0e38f;
#pragma unroll
            for (int c = 0; c < 16; c++) mx = fmaxf(mx, srow[seg * 16 + c]);
            mx = fmaxf(mx, __shfl_xor_sync(0xffffffffu, mx, 1));
            mx = fmaxf(mx, __shfl_xor_sync(0xffffffffu, mx, 2));
            float m_old = m_sm[row];
            float m_new = fmaxf(m_old, mx);
            float sum = 0.f;
#pragma unroll
            for (int c = 0; c < 16; c++) {
                float p = __expf(srow[seg * 16 + c] - m_new);
                srow[seg * 16 + c] = __uint_as_float(f2tf(p));
                sum += p;
            }
            sum += __shfl_xor_sync(0xffffffffu, sum, 1);
            sum += __shfl_xor_sync(0xffffffffu, sum, 2);
            if (seg == 0) {
                float alpha = __expf(m_old - m_new);
                l_sm[row] = l_sm[row] * alpha + sum;
                m_sm[row] = m_new;
                a_sm[row] = alpha;
            }
        }
        __syncthreads();

        // ---- O = O*alpha + P @ V via tf32 mma ----
        {
            const int ra = mq * 16 + lq;
            float al0 = a_sm[ra], al1 = a_sm[ra + 8];
#pragma unroll
            for (int nt = 0; nt < 8; nt++) {
                O[nt][0] *= al0; O[nt][1] *= al0;
                O[nt][2] *= al1; O[nt][3] *= al1;
            }
#pragma unroll
            for (int ks = 0; ks < 64; ks += 8) {
                int c0 = ks + lr;
                uint32_t a0 = __float_as_uint(Ss[ra * SS_STR + c0]);
                uint32_t a1 = __float_as_uint(Ss[(ra + 8) * SS_STR + c0]);
                uint32_t a2 = __float_as_uint(Ss[ra * SS_STR + c0 + 4]);
                uint32_t a3 = __float_as_uint(Ss[(ra + 8) * SS_STR + c0 + 4]);
#pragma unroll
                for (int nt = 0; nt < 8; nt++) {
                    int n = wh * 64 + nt * 8 + lq;
                    uint32_t b0 = __float_as_uint(Vs[c0 * VS_STR + n]);
                    uint32_t b1 = __float_as_uint(Vs[(c0 + 4) * VS_STR + n]);
                    mma_tf32(O[nt], a0, a1, a2, a3, b0, b1);
                }
            }
        }
        __syncthreads();
    }

    // ---- normalize + write ctx ----
    {
        const int ra = mq * 16 + lq;
        float inv0 = 1.0f / l_sm[ra];
        float inv1 = 1.0f / l_sm[ra + 8];
        float* Cp = ctx + ((size_t)(b * 2048 + qt * 64)) * 4096 + h * 128;
#pragma unroll
        for (int nt = 0; nt < 8; nt++) {
            int c = wh * 64 + nt * 8 + 2 * lr;
            *(float2*)(Cp + (size_t)ra * 4096 + c)       = make_float2(O[nt][0] * inv0, O[nt][1] * inv0);
            *(float2*)(Cp + (size_t)(ra + 8) * 4096 + c) = make_float2(O[nt][2] * inv1, O[nt][3] * inv1);
        }
    }
}

// =========================================================================
// launcher
// =========================================================================
extern "C" void kernel_launch(void* const* d_in, const int* in_sizes, int n_in,
                              void* d_out, int out_size)
{
    const float* q  = (const float*)d_in[0];
    const float* k  = (const float*)d_in[1];
    const float* v  = (const float*)d_in[2];
    const float* Wq = (const float*)d_in[3];
    const float* Wk = (const float*)d_in[4];
    const float* Wv = (const float*)d_in[5];
    const float* Wd = (const float*)d_in[6];
    float* out = (float*)d_out;

    float *Qp, *Kp, *Vp, *Cp;
    cudaGetSymbolAddress((void**)&Qp, g_Q);
    cudaGetSymbolAddress((void**)&Kp, g_K);
    cudaGetSymbolAddress((void**)&Vp, g_V);
    cudaGetSymbolAddress((void**)&Cp, g_ctx);

    const int ATTN_SMEM = 2 * 64 * QH_STR * 4 + (64 * VS_STR + 64 * SS_STR + 192) * 4;
    cudaFuncSetAttribute(gemm_f16,    cudaFuncAttributeMaxDynamicSharedMemorySize, GEMM_SMEM);
    cudaFuncSetAttribute(attn_kernel, cudaFuncAttributeMaxDynamicSharedMemorySize, ATTN_SMEM);

    // projections
    gemm_f16<<<dim3(4096 / 128, 32), 256, GEMM_SMEM>>>(Qp, q, Wq, 4096, 4096, 4096);
    gemm_f16<<<dim3(1024 / 128, 32), 256, GEMM_SMEM>>>(Kp, k, Wk, 4096, 1024, 4096);
    gemm_f16<<<dim3(1024 / 128, 32), 256, GEMM_SMEM>>>(Vp, v, Wv, 4096, 1024, 4096);

    // RoPE (fused Q+K)
    rope_all<<<dim3(4096, 10), dim3(64, 4)>>>(Qp, Kp);

    // attention
    attn_kernel<<<dim3(32, 32, 2), 256, ATTN_SMEM>>>(Cp, Qp, Kp, Vp);

    // output projection
    gemm_f16<<<dim3(4096 / 128, 32), 256, GEMM_SMEM>>>(out, Cp, Wd, 4096, 4096, 4096);
}

// round 9
// speedup vs baseline: 1.1419x; 1.1419x over previous
#include <cuda_runtime.h>
#include <cuda_fp16.h>
#include <cstdint>
#include <cstddef>

// ---------------- scratch ----------------
__device__ float g_Q[4096u * 4096u];
__device__ float g_K[4096u * 1024u];
__device__ float g_V[4096u * 1024u];
__device__ float g_ctx[4096u * 4096u];

// ---------------- helpers ----------------
__device__ __forceinline__ uint32_t smem_u32(const void* p) {
    uint32_t a;
    asm("{ .reg .u64 t; cvta.to.shared.u64 t, %1; cvt.u32.u64 %0, t; }" : "=r"(a) : "l"(p));
    return a;
}
__device__ __forceinline__ void mma_f16(float* c, uint32_t a0, uint32_t a1,
                                        uint32_t a2, uint32_t a3,
                                        uint32_t b0, uint32_t b1) {
    asm volatile(
        "mma.sync.aligned.m16n8k16.row.col.f32.f16.f16.f32 "
        "{%0,%1,%2,%3}, {%4,%5,%6,%7}, {%8,%9}, {%0,%1,%2,%3};\n"
        : "+f"(c[0]), "+f"(c[1]), "+f"(c[2]), "+f"(c[3])
        : "r"(a0), "r"(a1), "r"(a2), "r"(a3), "r"(b0), "r"(b1));
}
// load adjacent fp32 pair from smem -> packed half2
__device__ __forceinline__ uint32_t ldcvt(const float* p) {
    float2 v = *(const float2*)p;
    __half2 h = __floats2half2_rn(v.x, v.y);
    return *(uint32_t*)&h;
}
__device__ __forceinline__ uint32_t pack2(float x, float y) {
    __half2 h = __floats2half2_rn(x, y);
    return *(uint32_t*)&h;
}
#define CP_ASYNC16(dst, src) \
    asm volatile("cp.async.cg.shared.global [%0], [%1], 16;" :: "r"(dst), "l"(src) : "memory")
#define CP_COMMIT() asm volatile("cp.async.commit_group;" ::: "memory")
#define CP_WAIT1()  asm volatile("cp.async.wait_group 1;" ::: "memory")

// =========================================================================
// FP16 GEMM (cp.async 2-stage, occupancy 2):  C[M,N] = A[M,K] @ B[N,K]^T
// fp32 in smem (stride 40: conflict-free LDS.64), cvt->half2 at fragment
// load. Block 128x128, K-tile 32, 256 thr, warp tile 64x32, fp32 accum.
// =========================================================================
#define GA_STR 40                        // 32 data + 8 pad floats
#define NST 2
#define STGF (2 * 128 * GA_STR)          // floats per stage (A then B)
#define GEMM_SMEM (NST * STGF * 4)       // 81920 bytes -> 2 CTAs/SM

__global__ void __launch_bounds__(256, 2)
gemm_f16(float* __restrict__ C, const float* __restrict__ A,
         const float* __restrict__ B, int M, int N, int K)
{
    extern __shared__ float sm[];

    const int tid  = threadIdx.x;
    const int warp = tid >> 5, lane = tid & 31;
    const int wm = warp & 1, wn = warp >> 1;
    const int bm = blockIdx.y * 128, bn = blockIdx.x * 128;
    const int kTiles = K >> 5;

    const int r8 = tid >> 3;             // 0..31
    const int c8 = tid & 7;              // 0..7 (16B chunk)
    const uint32_t sbase = smem_u32(sm);

    auto issue = [&](int kt) {
        const int s = kt & (NST - 1);
        const uint32_t As = sbase + (uint32_t)(s * STGF) * 4;
        const uint32_t Bs = As + 128 * GA_STR * 4;
        const float* Ag = A + (size_t)bm * K + (size_t)kt * 32;
        const float* Bg = B + (size_t)bn * K + (size_t)kt * 32;
#pragma unroll
        for (int i = 0; i < 4; i++) {
            int r = r8 + i * 32;
            CP_ASYNC16(As + (uint32_t)(r * GA_STR + c8 * 4) * 4,
                       Ag + (size_t)r * K + c8 * 4);
        }
#pragma unroll
        for (int i = 0; i < 4; i++) {
            int r = r8 + i * 32;
            CP_ASYNC16(Bs + (uint32_t)(r * GA_STR + c8 * 4) * 4,
                       Bg + (size_t)r * K + c8 * 4);
        }
        CP_COMMIT();
    };

    float acc[4][4][4];
#pragma unroll
    for (int i = 0; i < 4; i++)
#pragma unroll
        for (int j = 0; j < 4; j++)
#pragma unroll
            for (int t = 0; t < 4; t++) acc[i][j][t] = 0.f;

    issue(0);

    for (int kt = 0; kt < kTiles; kt++) {
        if (kt + 1 < kTiles) issue(kt + 1);
        else CP_COMMIT();
        CP_WAIT1();                       // stage kt ready
        __syncthreads();

        const float* As_ = sm + (kt & (NST - 1)) * STGF;
        const float* Bs_ = As_ + 128 * GA_STR;
#pragma unroll
        for (int ks = 0; ks < 2; ks++) {              // two k16 steps
            uint32_t a[4][4], b[4][2];
            const int c0 = ks * 16 + 2 * (lane & 3);
#pragma unroll
            for (int mt = 0; mt < 4; mt++) {
                int r0 = wm * 64 + mt * 16 + (lane >> 2);
                a[mt][0] = ldcvt(As_ + r0 * GA_STR + c0);
                a[mt][1] = ldcvt(As_ + (r0 + 8) * GA_STR + c0);
                a[mt][2] = ldcvt(As_ + r0 * GA_STR + c0 + 8);
                a[mt][3] = ldcvt(As_ + (r0 + 8) * GA_STR + c0 + 8);
            }
#pragma unroll
            for (int nt = 0; nt < 4; nt++) {
                int n0 = wn * 32 + nt * 8 + (lane >> 2);
                b[nt][0] = ldcvt(Bs_ + n0 * GA_STR + c0);
                b[nt][1] = ldcvt(Bs_ + n0 * GA_STR + c0 + 8);
            }
#pragma unroll
            for (int mt = 0; mt < 4; mt++)
#pragma unroll
                for (int nt = 0; nt < 4; nt++)
                    mma_f16(acc[mt][nt], a[mt][0], a[mt][1], a[mt][2], a[mt][3],
                            b[nt][0], b[nt][1]);
        }
        __syncthreads();
    }

#pragma unroll
    for (int mt = 0; mt < 4; mt++) {
        int r0 = bm + wm * 64 + mt * 16 + (lane >> 2);
#pragma unroll
        for (int nt = 0; nt < 4; nt++) {
            int c0 = bn + wn * 32 + nt * 8 + ((lane & 3) << 1);
            float* c = acc[mt][nt];
            *(float2*)(C + (size_t)r0 * N + c0)       = make_float2(c[0], c[1]);
            *(float2*)(C + (size_t)(r0 + 8) * N + c0) = make_float2(c[2], c[3]);
        }
    }
}

// =========================================================================
// Fused RoPE: Q heads (0..31) and K heads (32..39), grid (4096,10), blk (64,4)
// =========================================================================
__global__ void rope_all(float* __restrict__ Q, float* __restrict__ K)
{
    int tok = blockIdx.x;
    int hh  = blockIdx.y * 4 + threadIdx.y;
    int d   = threadIdx.x;
    int s   = tok & 2047;
    float inv = exp2f((float)d * -0.20762050593046f);
    float ang = (float)s * inv;
    float sn, cs;
    sincosf(ang, &sn, &cs);
    float* p = (hh < 32) ? (Q + (size_t)tok * 4096 + hh * 128)
                         : (K + (size_t)tok * 1024 + (hh - 32) * 128);
    float x1 = p[d], x2 = p[d + 64];
    p[d]      = x1 * cs - x2 * sn;
    p[d + 64] = x2 * cs + x1 * sn;
}

// =========================================================================
// Causal flash attention: f16 mma for QK^T AND PV.
// Q,K as half2 in smem; V,S fp32 in smem (packed to half2 at fragment load).
// 256 threads, occupancy 2.
// =========================================================================
#define QH_STR 68    // half2 per Q/K row (64 data + 4 pad)
#define VS_STR 132   // fp32 per V row (128 + 4) — conflict-free column loads
#define SS_STR 72    // fp32 per S row (64 + 8) — conflict-free float2 loads

__global__ void __launch_bounds__(256, 2)
attn_kernel(float* __restrict__ ctx, const float* __restrict__ Qg,
            const float* __restrict__ Kg, const float* __restrict__ Vg)
{
    extern __shared__ float sm[];
    __half2* Qh = (__half2*)sm;                     // 64*68 half2
    __half2* Kh = Qh + 64 * QH_STR;
    float* Vs   = (float*)(Kh + 64 * QH_STR);       // 64*132 fp32
    float* Ss   = Vs + 64 * VS_STR;                 // 64*72 fp32
    float* m_sm = Ss + 64 * SS_STR;
    float* l_sm = m_sm + 64;
    float* a_sm = l_sm + 64;

    const int tid  = threadIdx.x;
    const int warp = tid >> 5, lane = tid & 31;
    const int lq = lane >> 2;
    const int lr = lane & 3;
    const int qt = 31 - (int)blockIdx.x;
    const int h  = blockIdx.y;
    const int b  = blockIdx.z;
    const int hkv = h >> 2;
    const float scale = 0.08838834764831845f;

    const int mq = warp & 3;
    const int wh = warp >> 2;

    // ---- load Q tile (scaled, half2) ----
    const float* Qp = Qg + ((size_t)(b * 2048 + qt * 64)) * 4096 + h * 128;
#pragma unroll
    for (int i = 0; i < 8; i++) {
        int f = tid + i * 256;
        int r = f >> 5, c4 = (f & 31) << 2;
        float4 v = *(const float4*)(Qp + (size_t)r * 4096 + c4);
        __half2 h0 = __floats2half2_rn(v.x * scale, v.y * scale);
        __half2 h1 = __floats2half2_rn(v.z * scale, v.w * scale);
        __half2* p = Qh + r * QH_STR + (f & 31) * 2;
        p[0] = h0; p[1] = h1;
    }
    if (tid < 64) { m_sm[tid] = -3.0e38f; l_sm[tid] = 0.f; }

    float O[8][4];
#pragma unroll
    for (int i = 0; i < 8; i++)
#pragma unroll
        for (int j = 0; j < 4; j++) O[i][j] = 0.f;

    __syncthreads();

    for (int kt = 0; kt <= qt; kt++) {
        // ---- load K (half2) and V (raw fp32) tiles ----
        const float* Kp = Kg + ((size_t)(b * 2048 + kt * 64)) * 1024 + hkv * 128;
        const float* Vp = Vg + ((size_t)(b * 2048 + kt * 64)) * 1024 + hkv * 128;
#pragma unroll
        for (int i = 0; i < 8; i++) {
            int f = tid + i * 256;
            int r = f >> 5, c4 = (f & 31) << 2;
            float4 kv = *(const float4*)(Kp + (size_t)r * 1024 + c4);
            __half2 h0 = __floats2half2_rn(kv.x, kv.y);
            __half2 h1 = __floats2half2_rn(kv.z, kv.w);
            __half2* p = Kh + r * QH_STR + (f & 31) * 2;
            p[0] = h0; p[1] = h1;
            *(float4*)(Vs + r * VS_STR + c4) = *(const float4*)(Vp + (size_t)r * 1024 + c4);
        }
        __syncthreads();

        // ---- S = Q @ K^T via f16 mma ----
        {
            float sacc[4][4];
#pragma unroll
            for (int nt = 0; nt < 4; nt++)
#pragma unroll
                for (int t = 0; t < 4; t++) sacc[nt][t] = 0.f;

            const int r0 = mq * 16 + lq;
#pragma unroll
            for (int ks = 0; ks < 8; ks++) {         // 8 k16 steps over K=128
                int c0 = ks * 8 + lr;                 // half2 col
                uint32_t a0 = *(const uint32_t*)(Qh + r0 * QH_STR + c0);
                uint32_t a1 = *(const uint32_t*)(Qh + (r0 + 8) * QH_STR + c0);
                uint32_t a2 = *(const uint32_t*)(Qh + r0 * QH_STR + c0 + 4);
                uint32_t a3 = *(const uint32_t*)(Qh + (r0 + 8) * QH_STR + c0 + 4);
#pragma unroll
                for (int nt = 0; nt < 4; nt++) {
                    int n0 = wh * 32 + nt * 8 + lq;
                    uint32_t b0 = *(const uint32_t*)(Kh + n0 * QH_STR + c0);
                    uint32_t b1 = *(const uint32_t*)(Kh + n0 * QH_STR + c0 + 4);
                    mma_f16(sacc[nt], a0, a1, a2, a3, b0, b1);
                }
            }
            bool diag = (kt == qt);
#pragma unroll
            for (int nt = 0; nt < 4; nt++) {
                int c = wh * 32 + nt * 8 + 2 * lr;
                float v0 = sacc[nt][0], v1 = sacc[nt][1];
                float v2 = sacc[nt][2], v3 = sacc[nt][3];
                int ra = mq * 16 + lq, rb2 = ra + 8;
                if (diag) {
                    if (c > ra)      v0 = -3.0e38f;
                    if (c + 1 > ra)  v1 = -3.0e38f;
                    if (c > rb2)     v2 = -3.0e38f;
                    if (c + 1 > rb2) v3 = -3.0e38f;
                }
                *(float2*)(Ss + ra * SS_STR + c)  = make_float2(v0, v1);
                *(float2*)(Ss + rb2 * SS_STR + c) = make_float2(v2, v3);
            }
        }
        __syncthreads();

        // ---- online softmax (fp32), P stored fp32 ----
        {
            int row = tid >> 2, seg = tid & 3;
            float* srow = Ss + row * SS_STR;
            float mx = -3.0e38f;
#pragma unroll
            for (int c = 0; c < 16; c++) mx = fmaxf(mx, srow[seg * 16 + c]);
            mx = fmaxf(mx, __shfl_xor_sync(0xffffffffu, mx, 1));
            mx = fmaxf(mx, __shfl_xor_sync(0xffffffffu, mx, 2));
            float m_old = m_sm[row];
            float m_new = fmaxf(m_old, mx);
            float sum = 0.f;
#pragma unroll
            for (int c = 0; c < 16; c++) {
                float p = __expf(srow[seg * 16 + c] - m_new);
                srow[seg * 16 + c] = p;
                sum += p;
            }
            sum += __shfl_xor_sync(0xffffffffu, sum, 1);
            sum += __shfl_xor_sync(0xffffffffu, sum, 2);
            if (seg == 0) {
                float alpha = __expf(m_old - m_new);
                l_sm[row] = l_sm[row] * alpha + sum;
                m_sm[row] = m_new;
                a_sm[row] = alpha;
            }
        }
        __syncthreads();

        // ---- O = O*alpha + P @ V via f16 mma ----
        {
            const int ra = mq * 16 + lq;
            float al0 = a_sm[ra], al1 = a_sm[ra + 8];
#pragma unroll
            for (int nt = 0; nt < 8; nt++) {
                O[nt][0] *= al0; O[nt][1] *= al0;
                O[nt][2] *= al1; O[nt][3] *= al1;
            }
#pragma unroll
            for (int ks = 0; ks < 4; ks++) {          // 4 k16 steps over 64 kv
                const int c0 = ks * 16 + 2 * lr;
                uint32_t a0 = ldcvt(Ss + ra * SS_STR + c0);
                uint32_t a1 = ldcvt(Ss + (ra + 8) * SS_STR + c0);
                uint32_t a2 = ldcvt(Ss + ra * SS_STR + c0 + 8);
                uint32_t a3 = ldcvt(Ss + (ra + 8) * SS_STR + c0 + 8);
#pragma unroll
                for (int nt = 0; nt < 8; nt++) {
                    int n = wh * 64 + nt * 8 + lq;
                    uint32_t b0 = pack2(Vs[c0 * VS_STR + n],       Vs[(c0 + 1) * VS_STR + n]);
                    uint32_t b1 = pack2(Vs[(c0 + 8) * VS_STR + n], Vs[(c0 + 9) * VS_STR + n]);
                    mma_f16(O[nt], a0, a1, a2, a3, b0, b1);
                }
            }
        }
        __syncthreads();
    }

    // ---- normalize + write ctx ----
    {
        const int ra = mq * 16 + lq;
        float inv0 = 1.0f / l_sm[ra];
        float inv1 = 1.0f / l_sm[ra + 8];
        float* Cp = ctx + ((size_t)(b * 2048 + qt * 64)) * 4096 + h * 128;
#pragma unroll
        for (int nt = 0; nt < 8; nt++) {
            int c = wh * 64 + nt * 8 + 2 * lr;
            *(float2*)(Cp + (size_t)ra * 4096 + c)       = make_float2(O[nt][0] * inv0, O[nt][1] * inv0);
            *(float2*)(Cp + (size_t)(ra + 8) * 4096 + c) = make_float2(O[nt][2] * inv1, O[nt][3] * inv1);
        }
    }
}

// =========================================================================
// launcher
// =========================================================================
extern "C" void kernel_launch(void* const* d_in, const int* in_sizes, int n_in,
                              void* d_out, int out_size)
{
    const float* q  = (const float*)d_in[0];
    const float* k  = (const float*)d_in[1];
    const float* v  = (const float*)d_in[2];
    const float* Wq = (const float*)d_in[3];
    const float* Wk = (const float*)d_in[4];
    const float* Wv = (const float*)d_in[5];
    const float* Wd = (const float*)d_in[6];
    float* out = (float*)d_out;

    float *Qp, *Kp, *Vp, *Cp;
    cudaGetSymbolAddress((void**)&Qp, g_Q);
    cudaGetSymbolAddress((void**)&Kp, g_K);
    cudaGetSymbolAddress((void**)&Vp, g_V);
    cudaGetSymbolAddress((void**)&Cp, g_ctx);

    const int ATTN_SMEM = 2 * 64 * QH_STR * 4 + (64 * VS_STR + 64 * SS_STR + 192) * 4;
    cudaFuncSetAttribute(gemm_f16,    cudaFuncAttributeMaxDynamicSharedMemorySize, GEMM_SMEM);
    cudaFuncSetAttribute(attn_kernel, cudaFuncAttributeMaxDynamicSharedMemorySize, ATTN_SMEM);

    // projections
    gemm_f16<<<dim3(4096 / 128, 32), 256, GEMM_SMEM>>>(Qp, q, Wq, 4096, 4096, 4096);
    gemm_f16<<<dim3(1024 / 128, 32), 256, GEMM_SMEM>>>(Kp, k, Wk, 4096, 1024, 4096);
    gemm_f16<<<dim3(1024 / 128, 32), 256, GEMM_SMEM>>>(Vp, v, Wv, 4096, 1024, 4096);

    // RoPE (fused Q+K)
    rope_all<<<dim3(4096, 10), dim3(64, 4)>>>(Qp, Kp);

    // attention
    attn_kernel<<<dim3(32, 32, 2), 256, ATTN_SMEM>>>(Cp, Qp, Kp, Vp);

    // output projection
    gemm_f16<<<dim3(4096 / 128, 32), 256, GEMM_SMEM>>>(out, Cp, Wd, 4096, 4096, 4096);
}

// round 10
// speedup vs baseline: 1.4208x; 1.2442x over previous
#include <cuda_runtime.h>
#include <cuda_fp16.h>
#include <cstdint>
#include <cstddef>

// ---------------- scratch ----------------
__device__ float g_Q[4096u * 4096u];   // projected Q (fp32, rope target)
__device__ float g_K[4096u * 1024u];
__device__ float g_V[4096u * 1024u];
__device__ __half h_q [16777216];      // fp16 copies of GEMM inputs
__device__ __half h_k [16777216];
__device__ __half h_v [16777216];
__device__ __half h_Wq[16777216];
__device__ __half h_Wk[ 4194304];
__device__ __half h_Wv[ 4194304];
__device__ __half h_Wd[16777216];
__device__ __half h_ctx[16777216];     // attention output (fp16)

// ---------------- helpers ----------------
__device__ __forceinline__ uint32_t smem_u32(const void* p) {
    uint32_t a;
    asm("{ .reg .u64 t; cvta.to.shared.u64 t, %1; cvt.u32.u64 %0, t; }" : "=r"(a) : "l"(p));
    return a;
}
__device__ __forceinline__ void mma_f16(float* c, uint32_t a0, uint32_t a1,
                                        uint32_t a2, uint32_t a3,
                                        uint32_t b0, uint32_t b1) {
    asm volatile(
        "mma.sync.aligned.m16n8k16.row.col.f32.f16.f16.f32 "
        "{%0,%1,%2,%3}, {%4,%5,%6,%7}, {%8,%9}, {%0,%1,%2,%3};\n"
        : "+f"(c[0]), "+f"(c[1]), "+f"(c[2]), "+f"(c[3])
        : "r"(a0), "r"(a1), "r"(a2), "r"(a3), "r"(b0), "r"(b1));
}
__device__ __forceinline__ void ldsm_x4(uint32_t& r0, uint32_t& r1,
                                        uint32_t& r2, uint32_t& r3, uint32_t addr) {
    asm volatile("ldmatrix.sync.aligned.m8n8.x4.shared.b16 {%0,%1,%2,%3}, [%4];"
        : "=r"(r0), "=r"(r1), "=r"(r2), "=r"(r3) : "r"(addr));
}
__device__ __forceinline__ void ldsm_x4t(uint32_t& r0, uint32_t& r1,
                                         uint32_t& r2, uint32_t& r3, uint32_t addr) {
    asm volatile("ldmatrix.sync.aligned.m8n8.x4.trans.shared.b16 {%0,%1,%2,%3}, [%4];"
        : "=r"(r0), "=r"(r1), "=r"(r2), "=r"(r3) : "r"(addr));
}
// load adjacent fp32 pair from smem -> packed half2
__device__ __forceinline__ uint32_t ldcvt(const float* p) {
    float2 v = *(const float2*)p;
    __half2 h = __floats2half2_rn(v.x, v.y);
    return *(uint32_t*)&h;
}
#define CP_ASYNC16(dst, src) \
    asm volatile("cp.async.cg.shared.global [%0], [%1], 16;" :: "r"(dst), "l"(src) : "memory")
#define CP_COMMIT() asm volatile("cp.async.commit_group;" ::: "memory")
#define CP_WAIT2()  asm volatile("cp.async.wait_group 2;" ::: "memory")

// =========================================================================
// fp32 -> fp16 bulk convert (vectorized)
// =========================================================================
__global__ void f2h(const float4* __restrict__ src, uint2* __restrict__ dst, int n4)
{
    int i = blockIdx.x * blockDim.x + threadIdx.x;
    if (i < n4) {
        float4 v = src[i];
        __half2 a = __floats2half2_rn(v.x, v.y);
        __half2 b = __floats2half2_rn(v.z, v.w);
        dst[i] = make_uint2(*(uint32_t*)&a, *(uint32_t*)&b);
    }
}

// =========================================================================
// FP16 GEMM (half gmem, cp.async 4-stage, ldmatrix, occ 2):
// C[M,N](fp32) = A[M,K] @ B[N,K]^T, A,B half. Block 128x128, K-tile 32,
// 256 thr (8 warps: 2m x 4n), warp tile 64x32. Row stride 40 half (80B).
// =========================================================================
#define AST 40                          // half per smem row (32 data + 8 pad)
#define NSTG 4
#define STGH (2 * 128 * AST)            // halves per stage (A then B)
#define GEMM_SMEM (NSTG * STGH * 2)     // 81920 B

__global__ void __launch_bounds__(256, 2)
gemm_f16(float* __restrict__ C, const __half* __restrict__ A,
         const __half* __restrict__ B, int M, int N, int K)
{
    extern __shared__ __half smh[];

    const int tid  = threadIdx.x;
    const int warp = tid >> 5, lane = tid & 31;
    const int wm = warp & 1, wn = warp >> 1;
    const int bm = blockIdx.y * 128, bn = blockIdx.x * 128;
    const int kTiles = K >> 5;
    const uint32_t sbase = smem_u32(smh);

    // cp.async mapping: A tile = 128 rows x 4 chunks(16B); 512 chunks; 2/thread
    auto issue = [&](int kt) {
        const int s = kt & (NSTG - 1);
        const uint32_t As = sbase + (uint32_t)(s * STGH) * 2;
        const uint32_t Bs = As + 128 * AST * 2;
        const __half* Ag = A + (size_t)bm * K + (size_t)kt * 32;
        const __half* Bg = B + (size_t)bn * K + (size_t)kt * 32;
#pragma unroll
        for (int i = 0; i < 2; i++) {
            int idx = tid + i * 256;
            int r = idx >> 2, c = idx & 3;
            CP_ASYNC16(As + (uint32_t)(r * 80 + c * 16), Ag + (size_t)r * K + c * 8);
        }
#pragma unroll
        for (int i = 0; i < 2; i++) {
            int idx = tid + i * 256;
            int r = idx >> 2, c = idx & 3;
            CP_ASYNC16(Bs + (uint32_t)(r * 80 + c * 16), Bg + (size_t)r * K + c * 8);
        }
        CP_COMMIT();
    };

    float acc[4][4][4];
#pragma unroll
    for (int i = 0; i < 4; i++)
#pragma unroll
        for (int j = 0; j < 4; j++)
#pragma unroll
            for (int t = 0; t < 4; t++) acc[i][j][t] = 0.f;

    // per-lane ldmatrix row/col offsets
    const int jj = lane >> 3, rim = lane & 7;        // matrix idx, row-in-matrix
    const int aRow = (jj & 1) * 8 + rim;             // + colh (jj>>1)*8
    const int aColh = (jj >> 1) * 8;
    const int bRow = (jj >> 1) * 8 + rim;
    const int bColh = (jj & 1) * 8;

    issue(0); issue(1); issue(2);

    for (int kt = 0; kt < kTiles; kt++) {
        CP_WAIT2();
        __syncthreads();
        if (kt + 3 < kTiles) issue(kt + 3);
        else CP_COMMIT();

        const int s = kt & (NSTG - 1);
        const uint32_t As = sbase + (uint32_t)(s * STGH) * 2;
        const uint32_t Bs = As + 128 * AST * 2;
#pragma unroll
        for (int ks = 0; ks < 2; ks++) {              // two k16 steps
            uint32_t a[4][4], b[4][2];
#pragma unroll
            for (int mt = 0; mt < 4; mt++) {
                int r = wm * 64 + mt * 16 + aRow;
                int ch = ks * 16 + aColh;
                ldsm_x4(a[mt][0], a[mt][1], a[mt][2], a[mt][3],
                        As + (uint32_t)(r * 80 + ch * 2));
            }
#pragma unroll
            for (int p = 0; p < 2; p++) {             // nt pairs
                int r = wn * 32 + p * 16 + bRow;
                int ch = ks * 16 + bColh;
                ldsm_x4(b[2 * p][0], b[2 * p][1], b[2 * p + 1][0], b[2 * p + 1][1],
                        Bs + (uint32_t)(r * 80 + ch * 2));
            }
#pragma unroll
            for (int mt = 0; mt < 4; mt++)
#pragma unroll
                for (int nt = 0; nt < 4; nt++)
                    mma_f16(acc[mt][nt], a[mt][0], a[mt][1], a[mt][2], a[mt][3],
                            b[nt][0], b[nt][1]);
        }
        __syncthreads();
    }

#pragma unroll
    for (int mt = 0; mt < 4; mt++) {
        int r0 = bm + wm * 64 + mt * 16 + (lane >> 2);
#pragma unroll
        for (int nt = 0; nt < 4; nt++) {
            int c0 = bn + wn * 32 + nt * 8 + ((lane & 3) << 1);
            float* c = acc[mt][nt];
            *(float2*)(C + (size_t)r0 * N + c0)       = make_float2(c[0], c[1]);
            *(float2*)(C + (size_t)(r0 + 8) * N + c0) = make_float2(c[2], c[3]);
        }
    }
}

// =========================================================================
// Fused RoPE
// =========================================================================
__global__ void rope_all(float* __restrict__ Q, float* __restrict__ K)
{
    int tok = blockIdx.x;
    int hh  = blockIdx.y * 4 + threadIdx.y;
    int d   = threadIdx.x;
    int s   = tok & 2047;
    float inv = exp2f((float)d * -0.20762050593046f);
    float ang = (float)s * inv;
    float sn, cs;
    sincosf(ang, &sn, &cs);
    float* p = (hh < 32) ? (Q + (size_t)tok * 4096 + hh * 128)
                         : (K + (size_t)tok * 1024 + (hh - 32) * 128);
    float x1 = p[d], x2 = p[d + 64];
    p[d]      = x1 * cs - x2 * sn;
    p[d + 64] = x2 * cs + x1 * sn;
}

// =========================================================================
// Causal flash attention: ldmatrix f16 mma QK + PV, fp32 softmax.
// Q/K/V half in smem (272B rows), S fp32. Output h_ctx fp16. occ 2.
// =========================================================================
#define QH 136       // half per Q/K/V smem row (128 data + 8 pad)
#define SS_STR 72    // fp32 per S row

__global__ void __launch_bounds__(256, 2)
attn_kernel(__half* __restrict__ ctx, const float* __restrict__ Qg,
            const float* __restrict__ Kg, const float* __restrict__ Vg)
{
    extern __shared__ float sm[];
    __half* Qh  = (__half*)sm;                      // 64*136 half
    __half* Kh  = Qh + 64 * QH;
    __half* Vh  = Kh + 64 * QH;                     // V as [kv][d]
    float* Ss   = (float*)(Vh + 64 * QH);           // 64*72 fp32
    float* m_sm = Ss + 64 * SS_STR;
    float* l_sm = m_sm + 64;
    float* a_sm = l_sm + 64;

    const int tid  = threadIdx.x;
    const int warp = tid >> 5, lane = tid & 31;
    const int lq = lane >> 2;
    const int lr = lane & 3;
    const int qt = 31 - (int)blockIdx.x;
    const int h  = blockIdx.y;
    const int b  = blockIdx.z;
    const int hkv = h >> 2;
    const float scale = 0.08838834764831845f;

    const int mq = warp & 3;
    const int wh = warp >> 2;

    const uint32_t qb = smem_u32(Qh), kb = smem_u32(Kh), vb = smem_u32(Vh);
    const int jj = lane >> 3, rim = lane & 7;

    // ---- load Q tile (scaled, half) ----
    const float* Qp = Qg + ((size_t)(b * 2048 + qt * 64)) * 4096 + h * 128;
#pragma unroll
    for (int i = 0; i < 8; i++) {
        int f = tid + i * 256;
        int r = f >> 5, c4 = (f & 31) << 2;
        float4 v = *(const float4*)(Qp + (size_t)r * 4096 + c4);
        __half2 h0 = __floats2half2_rn(v.x * scale, v.y * scale);
        __half2 h1 = __floats2half2_rn(v.z * scale, v.w * scale);
        __half2* p = (__half2*)(Qh + r * QH + c4);
        p[0] = h0; p[1] = h1;
    }
    if (tid < 64) { m_sm[tid] = -3.0e38f; l_sm[tid] = 0.f; }

    float O[8][4];
#pragma unroll
    for (int i = 0; i < 8; i++)
#pragma unroll
        for (int j = 0; j < 4; j++) O[i][j] = 0.f;

    __syncthreads();

    for (int kt = 0; kt <= qt; kt++) {
        // ---- load K, V tiles (half) ----
        const float* Kp = Kg + ((size_t)(b * 2048 + kt * 64)) * 1024 + hkv * 128;
        const float* Vp = Vg + ((size_t)(b * 2048 + kt * 64)) * 1024 + hkv * 128;
#pragma unroll
        for (int i = 0; i < 8; i++) {
            int f = tid + i * 256;
            int r = f >> 5, c4 = (f & 31) << 2;
            float4 kv = *(const float4*)(Kp + (size_t)r * 1024 + c4);
            __half2 h0 = __floats2half2_rn(kv.x, kv.y);
            __half2 h1 = __floats2half2_rn(kv.z, kv.w);
            __half2* p = (__half2*)(Kh + r * QH + c4);
            p[0] = h0; p[1] = h1;
            float4 vv = *(const float4*)(Vp + (size_t)r * 1024 + c4);
            __half2 v0 = __floats2half2_rn(vv.x, vv.y);
            __half2 v1 = __floats2half2_rn(vv.z, vv.w);
            __half2* pv = (__half2*)(Vh + r * QH + c4);
            pv[0] = v0; pv[1] = v1;
        }
        __syncthreads();

        // ---- S = Q @ K^T via ldmatrix + f16 mma ----
        {
            float sacc[4][4];
#pragma unroll
            for (int nt = 0; nt < 4; nt++)
#pragma unroll
                for (int t = 0; t < 4; t++) sacc[nt][t] = 0.f;

#pragma unroll
            for (int ks = 0; ks < 8; ks++) {          // 8 k16 steps over K=128
                uint32_t a[4], b[4][2];
                {
                    int r = mq * 16 + (jj & 1) * 8 + rim;
                    int ch = ks * 16 + (jj >> 1) * 8;
                    ldsm_x4(a[0], a[1], a[2], a[3], qb + (uint32_t)(r * 272 + ch * 2));
                }
#pragma unroll
                for (int p = 0; p < 2; p++) {
                    int r = wh * 32 + p * 16 + (jj >> 1) * 8 + rim;
                    int ch = ks * 16 + (jj & 1) * 8;
                    ldsm_x4(b[2 * p][0], b[2 * p][1], b[2 * p + 1][0], b[2 * p + 1][1],
                            kb + (uint32_t)(r * 272 + ch * 2));
                }
#pragma unroll
                for (int nt = 0; nt < 4; nt++)
                    mma_f16(sacc[nt], a[0], a[1], a[2], a[3], b[nt][0], b[nt][1]);
            }
            bool diag = (kt == qt);
#pragma unroll
            for (int nt = 0; nt < 4; nt++) {
                int c = wh * 32 + nt * 8 + 2 * lr;
                float v0 = sacc[nt][0], v1 = sacc[nt][1];
                float v2 = sacc[nt][2], v3 = sacc[nt][3];
                int ra = mq * 16 + lq, rb2 = ra + 8;
                if (diag) {
                    if (c > ra)      v0 = -3.0e38f;
                    if (c + 1 > ra)  v1 = -3.0e38f;
                    if (c > rb2)     v2 = -3.0e38f;
                    if (c + 1 > rb2) v3 = -3.0e38f;
                }
                *(float2*)(Ss + ra * SS_STR + c)  = make_float2(v0, v1);
                *(float2*)(Ss + rb2 * SS_STR + c) = make_float2(v2, v3);
            }
        }
        __syncthreads();

        // ---- online softmax (fp32) ----
        {
            int row = tid >> 2, seg = tid & 3;
            float* srow = Ss + row * SS_STR;
            float mx = -3.0e38f;
#pragma unroll
            for (int c = 0; c < 16; c++) mx = fmaxf(mx, srow[seg * 16 + c]);
            mx = fmaxf(mx, __shfl_xor_sync(0xffffffffu, mx, 1));
            mx = fmaxf(mx, __shfl_xor_sync(0xffffffffu, mx, 2));
            float m_old = m_sm[row];
            float m_new = fmaxf(m_old, mx);
            float sum = 0.f;
#pragma unroll
            for (int c = 0; c < 16; c++) {
                float p = __expf(srow[seg * 16 + c] - m_new);
                srow[seg * 16 + c] = p;
                sum += p;
            }
            sum += __shfl_xor_sync(0xffffffffu, sum, 1);
            sum += __shfl_xor_sync(0xffffffffu, sum, 2);
            if (seg == 0) {
                float alpha = __expf(m_old - m_new);
                l_sm[row] = l_sm[row] * alpha + sum;
                m_sm[row] = m_new;
                a_sm[row] = alpha;
            }
        }
        __syncthreads();

        // ---- O = O*alpha + P @ V (a: ldcvt from fp32 S; b: trans ldmatrix V)
        {
            const int ra = mq * 16 + lq;
            float al0 = a_sm[ra], al1 = a_sm[ra + 8];
#pragma unroll
            for (int nt = 0; nt < 8; nt++) {
                O[nt][0] *= al0; O[nt][1] *= al0;
                O[nt][2] *= al1; O[nt][3] *= al1;
            }
#pragma unroll
            for (int ks = 0; ks < 4; ks++) {          // 4 k16 steps over 64 kv
                const int c0 = ks * 16 + 2 * lr;
                uint32_t a0 = ldcvt(Ss + ra * SS_STR + c0);
                uint32_t a1 = ldcvt(Ss + (ra + 8) * SS_STR + c0);
                uint32_t a2 = ldcvt(Ss + ra * SS_STR + c0 + 8);
                uint32_t a3 = ldcvt(Ss + (ra + 8) * SS_STR + c0 + 8);
                uint32_t b[8][2];
#pragma unroll
                for (int p = 0; p < 4; p++) {         // 8 nt = 4 pairs
                    int kr = ks * 16 + (jj & 1) * 8 + rim;
                    int nc = wh * 64 + p * 16 + (jj >> 1) * 8;
                    ldsm_x4t(b[2 * p][0], b[2 * p][1], b[2 * p + 1][0], b[2 * p + 1][1],
                             vb + (uint32_t)(kr * 272 + nc * 2));
                }
#pragma unroll
                for (int nt = 0; nt < 8; nt++)
                    mma_f16(O[nt], a0, a1, a2, a3, b[nt][0], b[nt][1]);
            }
        }
        __syncthreads();
    }

    // ---- normalize + write ctx (fp16) ----
    {
        const int ra = mq * 16 + lq;
        float inv0 = 1.0f / l_sm[ra];
        float inv1 = 1.0f / l_sm[ra + 8];
        __half* Cp = ctx + ((size_t)(b * 2048 + qt * 64)) * 4096 + h * 128;
#pragma unroll
        for (int nt = 0; nt < 8; nt++) {
            int c = wh * 64 + nt * 8 + 2 * lr;
            *(__half2*)(Cp + (size_t)ra * 4096 + c) =
                __floats2half2_rn(O[nt][0] * inv0, O[nt][1] * inv0);
            *(__half2*)(Cp + (size_t)(ra + 8) * 4096 + c) =
                __floats2half2_rn(O[nt][2] * inv1, O[nt][3] * inv1);
        }
    }
}

// =========================================================================
// launcher
// =========================================================================
extern "C" void kernel_launch(void* const* d_in, const int* in_sizes, int n_in,
                              void* d_out, int out_size)
{
    const float* q  = (const float*)d_in[0];
    const float* k  = (const float*)d_in[1];
    const float* v  = (const float*)d_in[2];
    const float* Wq = (const float*)d_in[3];
    const float* Wk = (const float*)d_in[4];
    const float* Wv = (const float*)d_in[5];
    const float* Wd = (const float*)d_in[6];
    float* out = (float*)d_out;

    float *Qp, *Kp, *Vp;
    __half *hq, *hk, *hv, *hWq, *hWk, *hWv, *hWd, *hctx;
    cudaGetSymbolAddress((void**)&Qp, g_Q);
    cudaGetSymbolAddress((void**)&Kp, g_K);
    cudaGetSymbolAddress((void**)&Vp, g_V);
    cudaGetSymbolAddress((void**)&hq,  h_q);
    cudaGetSymbolAddress((void**)&hk,  h_k);
    cudaGetSymbolAddress((void**)&hv,  h_v);
    cudaGetSymbolAddress((void**)&hWq, h_Wq);
    cudaGetSymbolAddress((void**)&hWk, h_Wk);
    cudaGetSymbolAddress((void**)&hWv, h_Wv);
    cudaGetSymbolAddress((void**)&hWd, h_Wd);
    cudaGetSymbolAddress((void**)&hctx, h_ctx);

    const int ATTN_SMEM = 3 * 64 * QH * 2 + (64 * SS_STR + 192) * 4;
    cudaFuncSetAttribute(gemm_f16,    cudaFuncAttributeMaxDynamicSharedMemorySize, GEMM_SMEM);
    cudaFuncSetAttribute(attn_kernel, cudaFuncAttributeMaxDynamicSharedMemorySize, ATTN_SMEM);

    // fp32 -> fp16 input conversion
    const int big = 16777216 / 4, small = 4194304 / 4;
    f2h<<<(big + 255) / 256, 256>>>((const float4*)q,  (uint2*)hq,  big);
    f2h<<<(big + 255) / 256, 256>>>((const float4*)k,  (uint2*)hk,  big);
    f2h<<<(big + 255) / 256, 256>>>((const float4*)v,  (uint2*)hv,  big);
    f2h<<<(big + 255) / 256, 256>>>((const float4*)Wq, (uint2*)hWq, big);
    f2h<<<(small + 255) / 256, 256>>>((const float4*)Wk, (uint2*)hWk, small);
    f2h<<<(small + 255) / 256, 256>>>((const float4*)Wv, (uint2*)hWv, small);
    f2h<<<(big + 255) / 256, 256>>>((const float4*)Wd, (uint2*)hWd, big);

    // projections (fp16 in, fp32 out)
    gemm_f16<<<dim3(4096 / 128, 32), 256, GEMM_SMEM>>>(Qp, hq, hWq, 4096, 4096, 4096);
    gemm_f16<<<dim3(1024 / 128, 32), 256, GEMM_SMEM>>>(Kp, hk, hWk, 4096, 1024, 4096);
    gemm_f16<<<dim3(1024 / 128, 32), 256, GEMM_SMEM>>>(Vp, hv, hWv, 4096, 1024, 4096);

    // RoPE (fused Q+K)
    rope_all<<<dim3(4096, 10), dim3(64, 4)>>>(Qp, Kp);

    // attention (fp32 in, fp16 ctx out)
    attn_kernel<<<dim3(32, 32, 2), 256, ATTN_SMEM>>>(hctx, Qp, Kp, Vp);

    // output projection (fp16 in, fp32 out)
    gemm_f16<<<dim3(4096 / 128, 32), 256, GEMM_SMEM>>>(out, hctx, hWd, 4096, 4096, 4096);
}

// round 11
// speedup vs baseline: 1.4627x; 1.0295x over previous
#include <cuda_runtime.h>
#include <cuda_fp16.h>
#include <cstdint>
#include <cstddef>

// ---------------- scratch (all fp16) ----------------
__device__ __half h_q  [16777216];     // fp16 copies of GEMM inputs
__device__ __half h_k  [16777216];
__device__ __half h_v  [16777216];
__device__ __half h_Wq [16777216];
__device__ __half h_Wk [ 4194304];
__device__ __half h_Wv [ 4194304];
__device__ __half h_Wd [16777216];
__device__ __half h_Qp [16777216];     // projected Q (fp16, rope+scale applied)
__device__ __half h_Kp [ 4194304];     // projected K (fp16, rope applied)
__device__ __half h_Vp [ 4194304];     // projected V (fp16)
__device__ __half h_ctx[16777216];     // attention output (fp16)

// ---------------- helpers ----------------
__device__ __forceinline__ uint32_t smem_u32(const void* p) {
    uint32_t a;
    asm("{ .reg .u64 t; cvta.to.shared.u64 t, %1; cvt.u32.u64 %0, t; }" : "=r"(a) : "l"(p));
    return a;
}
__device__ __forceinline__ void mma_f16(float* c, uint32_t a0, uint32_t a1,
                                        uint32_t a2, uint32_t a3,
                                        uint32_t b0, uint32_t b1) {
    asm volatile(
        "mma.sync.aligned.m16n8k16.row.col.f32.f16.f16.f32 "
        "{%0,%1,%2,%3}, {%4,%5,%6,%7}, {%8,%9}, {%0,%1,%2,%3};\n"
        : "+f"(c[0]), "+f"(c[1]), "+f"(c[2]), "+f"(c[3])
        : "r"(a0), "r"(a1), "r"(a2), "r"(a3), "r"(b0), "r"(b1));
}
__device__ __forceinline__ void ldsm_x4(uint32_t& r0, uint32_t& r1,
                                        uint32_t& r2, uint32_t& r3, uint32_t addr) {
    asm volatile("ldmatrix.sync.aligned.m8n8.x4.shared.b16 {%0,%1,%2,%3}, [%4];"
        : "=r"(r0), "=r"(r1), "=r"(r2), "=r"(r3) : "r"(addr));
}
__device__ __forceinline__ void ldsm_x4t(uint32_t& r0, uint32_t& r1,
                                         uint32_t& r2, uint32_t& r3, uint32_t addr) {
    asm volatile("ldmatrix.sync.aligned.m8n8.x4.trans.shared.b16 {%0,%1,%2,%3}, [%4];"
        : "=r"(r0), "=r"(r1), "=r"(r2), "=r"(r3) : "r"(addr));
}
__device__ __forceinline__ uint32_t ldcvt(const float* p) {
    float2 v = *(const float2*)p;
    __half2 h = __floats2half2_rn(v.x, v.y);
    return *(uint32_t*)&h;
}
#define CP_ASYNC16(dst, src) \
    asm volatile("cp.async.cg.shared.global [%0], [%1], 16;" :: "r"(dst), "l"(src) : "memory")
#define CP_COMMIT() asm volatile("cp.async.commit_group;" ::: "memory")
#define CP_WAIT2()  asm volatile("cp.async.wait_group 2;" ::: "memory")

// =========================================================================
// fp32 -> fp16 bulk convert
// =========================================================================
__global__ void f2h(const float4* __restrict__ src, uint2* __restrict__ dst, int n4)
{
    int i = blockIdx.x * blockDim.x + threadIdx.x;
    if (i < n4) {
        float4 v = src[i];
        __half2 a = __floats2half2_rn(v.x, v.y);
        __half2 b = __floats2half2_rn(v.z, v.w);
        dst[i] = make_uint2(*(uint32_t*)&a, *(uint32_t*)&b);
    }
}

// =========================================================================
// FP16 GEMM (half gmem, cp.async 4-stage, ldmatrix, occ 2), templated output:
// C[M,N] = A[M,K] @ B[N,K]^T, A,B half, acc fp32, C fp32 or fp16.
// =========================================================================
#define AST 40
#define NSTG 4
#define STGH (2 * 128 * AST)
#define GEMM_SMEM (NSTG * STGH * 2)     // 81920 B

template <typename OT>
__global__ void __launch_bounds__(256, 2)
gemm_f16(OT* __restrict__ C, const __half* __restrict__ A,
         const __half* __restrict__ B, int M, int N, int K)
{
    extern __shared__ __half smh[];

    const int tid  = threadIdx.x;
    const int warp = tid >> 5, lane = tid & 31;
    const int wm = warp & 1, wn = warp >> 1;
    const int bm = blockIdx.y * 128, bn = blockIdx.x * 128;
    const int kTiles = K >> 5;
    const uint32_t sbase = smem_u32(smh);

    auto issue = [&](int kt) {
        const int s = kt & (NSTG - 1);
        const uint32_t As = sbase + (uint32_t)(s * STGH) * 2;
        const uint32_t Bs = As + 128 * AST * 2;
        const __half* Ag = A + (size_t)bm * K + (size_t)kt * 32;
        const __half* Bg = B + (size_t)bn * K + (size_t)kt * 32;
#pragma unroll
        for (int i = 0; i < 2; i++) {
            int idx = tid + i * 256;
            int r = idx >> 2, c = idx & 3;
            CP_ASYNC16(As + (uint32_t)(r * 80 + c * 16), Ag + (size_t)r * K + c * 8);
        }
#pragma unroll
        for (int i = 0; i < 2; i++) {
            int idx = tid + i * 256;
            int r = idx >> 2, c = idx & 3;
            CP_ASYNC16(Bs + (uint32_t)(r * 80 + c * 16), Bg + (size_t)r * K + c * 8);
        }
        CP_COMMIT();
    };

    float acc[4][4][4];
#pragma unroll
    for (int i = 0; i < 4; i++)
#pragma unroll
        for (int j = 0; j < 4; j++)
#pragma unroll
            for (int t = 0; t < 4; t++) acc[i][j][t] = 0.f;

    const int jj = lane >> 3, rim = lane & 7;
    const int aRow = (jj & 1) * 8 + rim;
    const int aColh = (jj >> 1) * 8;
    const int bRow = (jj >> 1) * 8 + rim;
    const int bColh = (jj & 1) * 8;

    issue(0); issue(1); issue(2);

    for (int kt = 0; kt < kTiles; kt++) {
        CP_WAIT2();
        __syncthreads();
        if (kt + 3 < kTiles) issue(kt + 3);
        else CP_COMMIT();

        const int s = kt & (NSTG - 1);
        const uint32_t As = sbase + (uint32_t)(s * STGH) * 2;
        const uint32_t Bs = As + 128 * AST * 2;
#pragma unroll
        for (int ks = 0; ks < 2; ks++) {
            uint32_t a[4][4], b[4][2];
#pragma unroll
            for (int mt = 0; mt < 4; mt++) {
                int r = wm * 64 + mt * 16 + aRow;
                int ch = ks * 16 + aColh;
                ldsm_x4(a[mt][0], a[mt][1], a[mt][2], a[mt][3],
                        As + (uint32_t)(r * 80 + ch * 2));
            }
#pragma unroll
            for (int p = 0; p < 2; p++) {
                int r = wn * 32 + p * 16 + bRow;
                int ch = ks * 16 + bColh;
                ldsm_x4(b[2 * p][0], b[2 * p][1], b[2 * p + 1][0], b[2 * p + 1][1],
                        Bs + (uint32_t)(r * 80 + ch * 2));
            }
#pragma unroll
            for (int mt = 0; mt < 4; mt++)
#pragma unroll
                for (int nt = 0; nt < 4; nt++)
                    mma_f16(acc[mt][nt], a[mt][0], a[mt][1], a[mt][2], a[mt][3],
                            b[nt][0], b[nt][1]);
        }
        __syncthreads();
    }

#pragma unroll
    for (int mt = 0; mt < 4; mt++) {
        int r0 = bm + wm * 64 + mt * 16 + (lane >> 2);
#pragma unroll
        for (int nt = 0; nt < 4; nt++) {
            int c0 = bn + wn * 32 + nt * 8 + ((lane & 3) << 1);
            float* c = acc[mt][nt];
            if constexpr (sizeof(OT) == 2) {
                *(__half2*)((__half*)C + (size_t)r0 * N + c0) =
                    __floats2half2_rn(c[0], c[1]);
                *(__half2*)((__half*)C + (size_t)(r0 + 8) * N + c0) =
                    __floats2half2_rn(c[2], c[3]);
            } else {
                *(float2*)((float*)C + (size_t)r0 * N + c0)       = make_float2(c[0], c[1]);
                *(float2*)((float*)C + (size_t)(r0 + 8) * N + c0) = make_float2(c[2], c[3]);
            }
        }
    }
}

// =========================================================================
// Fused RoPE on fp16 tensors; folds softmax scale into Q.
// grid (4096, 10), block (64, 4). hh<32: Q head, else K head.
// =========================================================================
__global__ void rope_h(__half* __restrict__ Q, __half* __restrict__ K)
{
    int tok = blockIdx.x;
    int hh  = blockIdx.y * 4 + threadIdx.y;
    int d   = threadIdx.x;
    int s   = tok & 2047;
    float inv = exp2f((float)d * -0.20762050593046f);
    float ang = (float)s * inv;
    float sn, cs;
    sincosf(ang, &sn, &cs);
    bool isQ = (hh < 32);
    float sc = isQ ? 0.08838834764831845f : 1.0f;
    __half* p = isQ ? (Q + (size_t)tok * 4096 + hh * 128)
                    : (K + (size_t)tok * 1024 + (hh - 32) * 128);
    float x1 = __half2float(p[d]), x2 = __half2float(p[d + 64]);
    p[d]      = __float2half((x1 * cs - x2 * sn) * sc);
    p[d + 64] = __float2half((x2 * cs + x1 * sn) * sc);
}

// =========================================================================
// Causal flash attention: all-fp16 tiles (pure uint4 copies in),
// ldmatrix f16 mma QK + PV, fp32 softmax. occ 2.
// =========================================================================
#define QH 136       // half per Q/K/V smem row (128 data + 8 pad)
#define SS_STR 72    // fp32 per S row

__global__ void __launch_bounds__(256, 2)
attn_kernel(__half* __restrict__ ctx, const __half* __restrict__ Qg,
            const __half* __restrict__ Kg, const __half* __restrict__ Vg)
{
    extern __shared__ float sm[];
    __half* Qh  = (__half*)sm;
    __half* Kh  = Qh + 64 * QH;
    __half* Vh  = Kh + 64 * QH;
    float* Ss   = (float*)(Vh + 64 * QH);
    float* m_sm = Ss + 64 * SS_STR;
    float* l_sm = m_sm + 64;
    float* a_sm = l_sm + 64;

    const int tid  = threadIdx.x;
    const int warp = tid >> 5, lane = tid & 31;
    const int lq = lane >> 2;
    const int lr = lane & 3;
    const int qt = 31 - (int)blockIdx.x;
    const int h  = blockIdx.y;
    const int b  = blockIdx.z;
    const int hkv = h >> 2;

    const int mq = warp & 3;
    const int wh = warp >> 2;

    const uint32_t qb = smem_u32(Qh), kb = smem_u32(Kh), vb = smem_u32(Vh);
    const int jj = lane >> 3, rim = lane & 7;

    // ---- load Q tile (pure copy; scale pre-folded in rope) ----
    const __half* Qp = Qg + ((size_t)(b * 2048 + qt * 64)) * 4096 + h * 128;
#pragma unroll
    for (int i = 0; i < 4; i++) {
        int f = tid + i * 256;                 // 1024 uint4 chunks
        int r = f >> 4, c = f & 15;
        *(uint4*)(Qh + r * QH + c * 8) = *(const uint4*)(Qp + (size_t)r * 4096 + c * 8);
    }
    if (tid < 64) { m_sm[tid] = -3.0e38f; l_sm[tid] = 0.f; }

    float O[8][4];
#pragma unroll
    for (int i = 0; i < 8; i++)
#pragma unroll
        for (int j = 0; j < 4; j++) O[i][j] = 0.f;

    __syncthreads();

    for (int kt = 0; kt <= qt; kt++) {
        // ---- load K, V tiles (pure copies) ----
        const __half* Kp = Kg + ((size_t)(b * 2048 + kt * 64)) * 1024 + hkv * 128;
        const __half* Vp = Vg + ((size_t)(b * 2048 + kt * 64)) * 1024 + hkv * 128;
#pragma unroll
        for (int i = 0; i < 4; i++) {
            int f = tid + i * 256;
            int r = f >> 4, c = f & 15;
            *(uint4*)(Kh + r * QH + c * 8) = *(const uint4*)(Kp + (size_t)r * 1024 + c * 8);
            *(uint4*)(Vh + r * QH + c * 8) = *(const uint4*)(Vp + (size_t)r * 1024 + c * 8);
        }
        __syncthreads();

        // ---- S = Q @ K^T via ldmatrix + f16 mma ----
        {
            float sacc[4][4];
#pragma unroll
            for (int nt = 0; nt < 4; nt++)
#pragma unroll
                for (int t = 0; t < 4; t++) sacc[nt][t] = 0.f;

#pragma unroll
            for (int ks = 0; ks < 8; ks++) {
                uint32_t a[4], b2[4][2];
                {
                    int r = mq * 16 + (jj & 1) * 8 + rim;
                    int ch = ks * 16 + (jj >> 1) * 8;
                    ldsm_x4(a[0], a[1], a[2], a[3], qb + (uint32_t)(r * 272 + ch * 2));
                }
#pragma unroll
                for (int p = 0; p < 2; p++) {
                    int r = wh * 32 + p * 16 + (jj >> 1) * 8 + rim;
                    int ch = ks * 16 + (jj & 1) * 8;
                    ldsm_x4(b2[2 * p][0], b2[2 * p][1], b2[2 * p + 1][0], b2[2 * p + 1][1],
                            kb + (uint32_t)(r * 272 + ch * 2));
                }
#pragma unroll
                for (int nt = 0; nt < 4; nt++)
                    mma_f16(sacc[nt], a[0], a[1], a[2], a[3], b2[nt][0], b2[nt][1]);
            }
            bool diag = (kt == qt);
#pragma unroll
            for (int nt = 0; nt < 4; nt++) {
                int c = wh * 32 + nt * 8 + 2 * lr;
                float v0 = sacc[nt][0], v1 = sacc[nt][1];
                float v2 = sacc[nt][2], v3 = sacc[nt][3];
                int ra = mq * 16 + lq, rb2 = ra + 8;
                if (diag) {
                    if (c > ra)      v0 = -3.0e38f;
                    if (c + 1 > ra)  v1 = -3.0e38f;
                    if (c > rb2)     v2 = -3.0e38f;
                    if (c + 1 > rb2) v3 = -3.0e38f;
                }
                *(float2*)(Ss + ra * SS_STR + c)  = make_float2(v0, v1);
                *(float2*)(Ss + rb2 * SS_STR + c) = make_float2(v2, v3);
            }
        }
        __syncthreads();

        // ---- online softmax (fp32) ----
        {
            int row = tid >> 2, seg = tid & 3;
            float* srow = Ss + row * SS_STR;
            float mx = -3.0e38f;
#pragma unroll
            for (int c = 0; c < 16; c++) mx = fmaxf(mx, srow[seg * 16 + c]);
            mx = fmaxf(mx, __shfl_xor_sync(0xffffffffu, mx, 1));
            mx = fmaxf(mx, __shfl_xor_sync(0xffffffffu, mx, 2));
            float m_old = m_sm[row];
            float m_new = fmaxf(m_old, mx);
            float sum = 0.f;
#pragma unroll
            for (int c = 0; c < 16; c++) {
                float p = __expf(srow[seg * 16 + c] - m_new);
                srow[seg * 16 + c] = p;
                sum += p;
            }
            sum += __shfl_xor_sync(0xffffffffu, sum, 1);
            sum += __shfl_xor_sync(0xffffffffu, sum, 2);
            if (seg == 0) {
                float alpha = __expf(m_old - m_new);
                l_sm[row] = l_sm[row] * alpha + sum;
                m_sm[row] = m_new;
                a_sm[row] = alpha;
            }
        }
        __syncthreads();

        // ---- O = O*alpha + P @ V ----
        {
            const int ra = mq * 16 + lq;
            float al0 = a_sm[ra], al1 = a_sm[ra + 8];
#pragma unroll
            for (int nt = 0; nt < 8; nt++) {
                O[nt][0] *= al0; O[nt][1] *= al0;
                O[nt][2] *= al1; O[nt][3] *= al1;
            }
#pragma unroll
            for (int ks = 0; ks < 4; ks++) {
                const int c0 = ks * 16 + 2 * lr;
                uint32_t a0 = ldcvt(Ss + ra * SS_STR + c0);
                uint32_t a1 = ldcvt(Ss + (ra + 8) * SS_STR + c0);
                uint32_t a2 = ldcvt(Ss + ra * SS_STR + c0 + 8);
                uint32_t a3 = ldcvt(Ss + (ra + 8) * SS_STR + c0 + 8);
                uint32_t b2[8][2];
#pragma unroll
                for (int p = 0; p < 4; p++) {
                    int kr = ks * 16 + (jj & 1) * 8 + rim;
                    int nc = wh * 64 + p * 16 + (jj >> 1) * 8;
                    ldsm_x4t(b2[2 * p][0], b2[2 * p][1], b2[2 * p + 1][0], b2[2 * p + 1][1],
                             vb + (uint32_t)(kr * 272 + nc * 2));
                }
#pragma unroll
                for (int nt = 0; nt < 8; nt++)
                    mma_f16(O[nt], a0, a1, a2, a3, b2[nt][0], b2[nt][1]);
            }
        }
        __syncthreads();
    }

    // ---- normalize + write ctx (fp16) ----
    {
        const int ra = mq * 16 + lq;
        float inv0 = 1.0f / l_sm[ra];
        float inv1 = 1.0f / l_sm[ra + 8];
        __half* Cp = ctx + ((size_t)(b * 2048 + qt * 64)) * 4096 + h * 128;
#pragma unroll
        for (int nt = 0; nt < 8; nt++) {
            int c = wh * 64 + nt * 8 + 2 * lr;
            *(__half2*)(Cp + (size_t)ra * 4096 + c) =
                __floats2half2_rn(O[nt][0] * inv0, O[nt][1] * inv0);
            *(__half2*)(Cp + (size_t)(ra + 8) * 4096 + c) =
                __floats2half2_rn(O[nt][2] * inv1, O[nt][3] * inv1);
        }
    }
}

// =========================================================================
// launcher
// =========================================================================
extern "C" void kernel_launch(void* const* d_in, const int* in_sizes, int n_in,
                              void* d_out, int out_size)
{
    const float* q  = (const float*)d_in[0];
    const float* k  = (const float*)d_in[1];
    const float* v  = (const float*)d_in[2];
    const float* Wq = (const float*)d_in[3];
    const float* Wk = (const float*)d_in[4];
    const float* Wv = (const float*)d_in[5];
    const float* Wd = (const float*)d_in[6];
    float* out = (float*)d_out;

    __half *hq, *hk, *hv, *hWq, *hWk, *hWv, *hWd, *hQp, *hKp, *hVp, *hctx;
    cudaGetSymbolAddress((void**)&hq,  h_q);
    cudaGetSymbolAddress((void**)&hk,  h_k);
    cudaGetSymbolAddress((void**)&hv,  h_v);
    cudaGetSymbolAddress((void**)&hWq, h_Wq);
    cudaGetSymbolAddress((void**)&hWk, h_Wk);
    cudaGetSymbolAddress((void**)&hWv, h_Wv);
    cudaGetSymbolAddress((void**)&hWd, h_Wd);
    cudaGetSymbolAddress((void**)&hQp, h_Qp);
    cudaGetSymbolAddress((void**)&hKp, h_Kp);
    cudaGetSymbolAddress((void**)&hVp, h_Vp);
    cudaGetSymbolAddress((void**)&hctx, h_ctx);

    const int ATTN_SMEM = 3 * 64 * QH * 2 + (64 * SS_STR + 192) * 4;
    cudaFuncSetAttribute(gemm_f16<__half>, cudaFuncAttributeMaxDynamicSharedMemorySize, GEMM_SMEM);
    cudaFuncSetAttribute(gemm_f16<float>,  cudaFuncAttributeMaxDynamicSharedMemorySize, GEMM_SMEM);
    cudaFuncSetAttribute(attn_kernel,      cudaFuncAttributeMaxDynamicSharedMemorySize, ATTN_SMEM);

    // fp32 -> fp16 input conversion
    const int big = 16777216 / 4, small = 4194304 / 4;
    f2h<<<(big + 255) / 256, 256>>>((const float4*)q,  (uint2*)hq,  big);
    f2h<<<(big + 255) / 256, 256>>>((const float4*)k,  (uint2*)hk,  big);
    f2h<<<(big + 255) / 256, 256>>>((const float4*)v,  (uint2*)hv,  big);
    f2h<<<(big + 255) / 256, 256>>>((const float4*)Wq, (uint2*)hWq, big);
    f2h<<<(small + 255) / 256, 256>>>((const float4*)Wk, (uint2*)hWk, small);
    f2h<<<(small + 255) / 256, 256>>>((const float4*)Wv, (uint2*)hWv, small);
    f2h<<<(big + 255) / 256, 256>>>((const float4*)Wd, (uint2*)hWd, big);

    // projections (fp16 in, fp16 out)
    gemm_f16<__half><<<dim3(4096 / 128, 32), 256, GEMM_SMEM>>>(hQp, hq, hWq, 4096, 4096, 4096);
    gemm_f16<__half><<<dim3(1024 / 128, 32), 256, GEMM_SMEM>>>(hKp, hk, hWk, 4096, 1024, 4096);
    gemm_f16<__half><<<dim3(1024 / 128, 32), 256, GEMM_SMEM>>>(hVp, hv, hWv, 4096, 1024, 4096);

    // RoPE on fp16 (Q scale folded)
    rope_h<<<dim3(4096, 10), dim3(64, 4)>>>(hQp, hKp);

    // attention (fp16 in, fp16 out)
    attn_kernel<<<dim3(32, 32, 2), 256, ATTN_SMEM>>>(hctx, hQp, hKp, hVp);

    // output projection (fp16 in, fp32 out)
    gemm_f16<float><<<dim3(4096 / 128, 32), 256, GEMM_SMEM>>>(out, hctx, hWd, 4096, 4096, 4096);
}